// round 11
// baseline (speedup 1.0000x reference)
#include <cuda_runtime.h>
#include <cstdint>

// Problem constants
#define BATCH 2
#define SEQ   2048
#define HID   2048
#define NHEAD 16
#define HDIM  128
#define MROWS (BATCH * SEQ)   // 4096
#define K3    (3 * HID)       // 6144

// Scratch (allocation-free rule: __device__ globals)
__device__ float g_qkv[(size_t)MROWS * K3];   // [4096, 6144]
__device__ float g_ctx[(size_t)MROWS * HID];  // [4096, 2048]
__device__ float g_x  [(size_t)MROWS * HID];  // tf32-truncated x
__device__ float g_wq [(size_t)HID * K3];     // tf32-truncated w_qkv [2048][6144]
__device__ float g_wo [(size_t)HID * HID];    // tf32-truncated w_out [2048][2048]

__device__ __forceinline__ unsigned f2tf(float x) {
    unsigned u;
    asm("cvt.rna.tf32.f32 %0, %1;" : "=r"(u) : "f"(x));
    return u;
}

__device__ __forceinline__ void mma_tf32(float* d, const unsigned* a, const unsigned* b) {
    asm volatile(
        "mma.sync.aligned.m16n8k8.row.col.f32.tf32.tf32.f32 "
        "{%0,%1,%2,%3},{%4,%5,%6,%7},{%8,%9},{%0,%1,%2,%3};"
        : "+f"(d[0]), "+f"(d[1]), "+f"(d[2]), "+f"(d[3])
        : "r"(a[0]), "r"(a[1]), "r"(a[2]), "r"(a[3]), "r"(b[0]), "r"(b[1]));
}

__device__ __forceinline__ void cp16(unsigned dst, const void* src) {
    asm volatile("cp.async.cg.shared.global [%0], [%1], 16;\n" :: "r"(dst), "l"(src));
}

// ===========================================================================
// tf32 truncating copy (inputs -> scratch), run once per launch
// ===========================================================================
__global__ void trunc_copy_kernel(const float4* __restrict__ src,
                                  float4* __restrict__ dst, int n4) {
    int i = blockIdx.x * blockDim.x + threadIdx.x;
    if (i < n4) {
        float4 v = src[i];
        v.x = __uint_as_float(f2tf(v.x));
        v.y = __uint_as_float(f2tf(v.y));
        v.z = __uint_as_float(f2tf(v.z));
        v.w = __uint_as_float(f2tf(v.w));
        dst[i] = v;
    }
}

// ===========================================================================
// tf32 mma.sync GEMM: C[M,N] = A[M,K] @ B[K,N] + bias
// Block 128x256, BK=32, 256 threads (8 warps, 2m x 4n, warp tile 64x64).
// A smem [m][k] XOR-swizzled (conflict-free LDS.64 fragments).
// B smem [k][n] stride 260 (pad) -> conflict-free LDS.32 fragments.
// 3-stage cp.async pipeline, inputs pre-truncated to tf32 (no mainloop CVT).
// ===========================================================================
#define GA_W 4096                   // A stage words (128*32)
#define GB_W 8320                   // B stage words (32*260)
#define GSTAGE_W (GA_W + GB_W)      // 12416 words
#define GBSTR 260
#define G_SMEM_BYTES (3 * GSTAGE_W * 4)   // 148992

template <bool TRUNC_OUT>
__global__ __launch_bounds__(256, 1)
void sgemm_tf32_kernel(const float* __restrict__ A, const float* __restrict__ Bw,
                       const float* __restrict__ bias, float* __restrict__ C,
                       int N, int K) {
    extern __shared__ float sm[];
    const int tid = threadIdx.x;
    const int lane = tid & 31;
    const int warp = tid >> 5;
    const int wm = warp & 1;        // 0..1  (64-row half)
    const int wn = warp >> 1;       // 0..3  (64-col quarter)
    const int bm = blockIdx.y * 128;
    const int bn = blockIdx.x * 256;

    const int g = lane >> 2;        // 0..7
    const int c = lane & 3;         // 0..3
    const int swz = (g & 3) * 8;

    unsigned smu;
    { unsigned long long p = __cvta_generic_to_shared(sm); smu = (unsigned)p; }

    // copy mapping: A 4 chunks of 16B, B 8 chunks of 16B per stage
    unsigned aDst[4]; const float* aSrc[4];
#pragma unroll
    for (int r = 0; r < 4; r++) {
        int a = tid + 256 * r;
        int row = a >> 3, cc = a & 7;
        aDst[r] = smu + (unsigned)(row * 32 + ((cc * 4) ^ ((row & 3) * 8))) * 4;
        aSrc[r] = A + (size_t)(bm + row) * K + cc * 4;
    }
    unsigned bDst[8]; const float* bSrc[8];
#pragma unroll
    for (int r = 0; r < 8; r++) {
        int bI = tid + 256 * r;
        int row = bI >> 6, cw = (bI & 63) * 4;
        bDst[r] = smu + (unsigned)(GA_W + row * GBSTR + cw) * 4;
        bSrc[r] = Bw + (size_t)row * N + bn + cw;
    }

    float acc[4][8][4];
#pragma unroll
    for (int mt = 0; mt < 4; mt++)
#pragma unroll
        for (int nt = 0; nt < 8; nt++)
#pragma unroll
            for (int r = 0; r < 4; r++) acc[mt][nt][r] = 0.f;

    const int T = K / 32;

    auto issue = [&](int i) {
        const unsigned so = (unsigned)((i % 3) * GSTAGE_W) * 4;
        const int k0 = i * 32;
#pragma unroll
        for (int r = 0; r < 4; r++) cp16(aDst[r] + so, aSrc[r] + k0);
#pragma unroll
        for (int r = 0; r < 8; r++) cp16(bDst[r] + so, bSrc[r] + (size_t)k0 * N);
    };

    issue(0);
    asm volatile("cp.async.commit_group;\n");
    issue(1);
    asm volatile("cp.async.commit_group;\n");

    for (int i = 0; i < T; i++) {
        asm volatile("cp.async.wait_group 1;\n");
        __syncthreads();

        if (i + 2 < T) issue(i + 2);
        asm volatile("cp.async.commit_group;\n");

        const float* As = sm + (i % 3) * GSTAGE_W;
        const float* Bs = As + GA_W;

#pragma unroll
        for (int s = 0; s < 4; s++) {
            const int kof = (8 * s + 2 * c) ^ swz;
            unsigned av[4][4];
#pragma unroll
            for (int mt = 0; mt < 4; mt++) {
                const float* pa = As + (wm * 64 + mt * 16 + g) * 32 + kof;
                float2 f0 = *(const float2*)pa;
                float2 f1 = *(const float2*)(pa + 8 * 32);
                av[mt][0] = __float_as_uint(f0.x);
                av[mt][2] = __float_as_uint(f0.y);
                av[mt][1] = __float_as_uint(f1.x);
                av[mt][3] = __float_as_uint(f1.y);
            }
            const float* pbBase = Bs + (8 * s + 2 * c) * GBSTR + wn * 64 + g;
#pragma unroll
            for (int nt = 0; nt < 8; nt++) {
                unsigned bv[2];
                bv[0] = __float_as_uint(pbBase[nt * 8]);
                bv[1] = __float_as_uint(pbBase[nt * 8 + GBSTR]);
#pragma unroll
                for (int mt = 0; mt < 4; mt++)
                    mma_tf32(acc[mt][nt], av[mt], bv);
            }
        }
        __syncthreads();
    }

    // epilogue: add bias, write float2 pairs
#pragma unroll
    for (int mt = 0; mt < 4; mt++) {
        const int row = bm + wm * 64 + mt * 16 + g;
#pragma unroll
        for (int nt = 0; nt < 8; nt++) {
            const int col = bn + wn * 64 + nt * 8 + 2 * c;
            const float b0 = __ldg(&bias[col]);
            const float b1 = __ldg(&bias[col + 1]);
            float v00 = acc[mt][nt][0] + b0, v01 = acc[mt][nt][1] + b1;
            float v10 = acc[mt][nt][2] + b0, v11 = acc[mt][nt][3] + b1;
            if (TRUNC_OUT) {
                v00 = __uint_as_float(f2tf(v00));
                v01 = __uint_as_float(f2tf(v01));
                v10 = __uint_as_float(f2tf(v10));
                v11 = __uint_as_float(f2tf(v11));
            }
            float2 o0 = {v00, v01}, o1 = {v10, v11};
            *(float2*)(C + (size_t)row * N + col) = o0;
            *(float2*)(C + (size_t)(row + 8) * N + col) = o1;
        }
    }
}

// ===========================================================================
// Tensor-core causal flash attention (tf32 mma.sync) — round 5 version
// ===========================================================================
#define K_STW 8192
#define V_STW 8448
#define V_BASE_W 16384
#define AT_SMEM_BYTES ((V_BASE_W + 2 * V_STW) * 4)   // 133120

__global__ __launch_bounds__(256, 1)
void flash_attn_tc_kernel(const float* __restrict__ qkv, float* __restrict__ ctx) {
    extern __shared__ float sm[];
    const int tid = threadIdx.x;
    const int lane = tid & 31;
    const int wid = tid >> 5;
    const int g = lane >> 2;
    const int c = lane & 3;
    const int qt = 15 - blockIdx.x;
    const int h = blockIdx.y;
    const int b = blockIdx.z;
    const int q0 = qt * 128;
    const float scale = 0.08838834764831845f;

    const float* base = qkv + ((size_t)b * SEQ) * K3 + (size_t)h * (3 * HDIM);

    unsigned smu;
    { unsigned long long p = __cvta_generic_to_shared(sm); smu = (unsigned)p; }

    const int ntiles = 2 * qt + 2;

    auto issue_tile = [&](int j, int st) {
        const float* kvb = base + (size_t)(j * 64) * K3;
#pragma unroll
        for (int r = 0; r < 8; r++) {
            int chunk = tid + 256 * r;
            int row = chunk >> 5;
            int cw = (chunk & 31) * 4;
            const float* src = kvb + (size_t)row * K3 + cw;
            unsigned kd = smu + (unsigned)(st * K_STW + row * 128 + (cw ^ ((row & 3) * 8))) * 4;
            unsigned vd = smu + (unsigned)(V_BASE_W + st * V_STW + row * 132 + cw) * 4;
            cp16(kd, src + HDIM);
            cp16(vd, src + 2 * HDIM);
        }
    };

    issue_tile(0, 0);
    asm volatile("cp.async.commit_group;\n");

    unsigned qf[16][4];
    {
        const float* qrow = base + (size_t)(q0 + wid * 16 + g) * K3;
        const float* qrow8 = qrow + 8 * (size_t)K3;
#pragma unroll
        for (int s = 0; s < 16; s++) {
            float2 f0 = *(const float2*)(qrow + 8 * s + 2 * c);
            float2 f1 = *(const float2*)(qrow8 + 8 * s + 2 * c);
            qf[s][0] = __float_as_uint(f0.x);
            qf[s][2] = __float_as_uint(f0.y);
            qf[s][1] = __float_as_uint(f1.x);
            qf[s][3] = __float_as_uint(f1.y);
        }
    }

    float o[16][4];
#pragma unroll
    for (int nt = 0; nt < 16; nt++)
#pragma unroll
        for (int r = 0; r < 4; r++) o[nt][r] = 0.f;
    float m0 = -1e30f, m1 = -1e30f, l0 = 0.f, l1 = 0.f;

    const int rowg0 = q0 + wid * 16 + g;
    const int rowg1 = rowg0 + 8;

    for (int j = 0; j < ntiles; j++) {
        if (j + 1 < ntiles) issue_tile(j + 1, (j + 1) & 1);
        asm volatile("cp.async.commit_group;\n");
        asm volatile("cp.async.wait_group 1;\n");
        __syncthreads();

        const int st = j & 1;
        const float* Ks = sm + st * K_STW;
        const float* Vs = sm + V_BASE_W + st * V_STW;

        float sv[8][4];
#pragma unroll
        for (int nt = 0; nt < 8; nt++)
#pragma unroll
            for (int r = 0; r < 4; r++) sv[nt][r] = 0.f;

#pragma unroll
        for (int s = 0; s < 16; s++) {
            const int kof = (8 * s + 2 * c) ^ ((g & 3) * 8);
#pragma unroll
            for (int nt = 0; nt < 8; nt++) {
                float2 kf = *(const float2*)(Ks + (nt * 8 + g) * 128 + kof);
                unsigned bv[2] = {__float_as_uint(kf.x), __float_as_uint(kf.y)};
                mma_tf32(sv[nt], qf[s], bv);
            }
        }

#pragma unroll
        for (int nt = 0; nt < 8; nt++)
#pragma unroll
            for (int r = 0; r < 4; r++) sv[nt][r] *= scale;

        if (j >= 2 * qt) {
            const int kv0 = j * 64;
#pragma unroll
            for (int nt = 0; nt < 8; nt++) {
                const int col = kv0 + nt * 8 + 2 * c;
                if (col     > rowg0) sv[nt][0] = -1e30f;
                if (col + 1 > rowg0) sv[nt][1] = -1e30f;
                if (col     > rowg1) sv[nt][2] = -1e30f;
                if (col + 1 > rowg1) sv[nt][3] = -1e30f;
            }
        }

        float mx0 = -1e30f, mx1 = -1e30f;
#pragma unroll
        for (int nt = 0; nt < 8; nt++) {
            mx0 = fmaxf(mx0, fmaxf(sv[nt][0], sv[nt][1]));
            mx1 = fmaxf(mx1, fmaxf(sv[nt][2], sv[nt][3]));
        }
        mx0 = fmaxf(mx0, __shfl_xor_sync(0xffffffffu, mx0, 1));
        mx0 = fmaxf(mx0, __shfl_xor_sync(0xffffffffu, mx0, 2));
        mx1 = fmaxf(mx1, __shfl_xor_sync(0xffffffffu, mx1, 1));
        mx1 = fmaxf(mx1, __shfl_xor_sync(0xffffffffu, mx1, 2));

        const float mn0 = fmaxf(m0, mx0);
        const float mn1 = fmaxf(m1, mx1);
        const float a0 = __expf(m0 - mn0);
        const float a1 = __expf(m1 - mn1);
        m0 = mn0; m1 = mn1;

        float l0a = 0.f, l1a = 0.f;
        unsigned pf[8][4];
#pragma unroll
        for (int nt = 0; nt < 8; nt++) {
            float p0 = __expf(sv[nt][0] - mn0);
            float p1 = __expf(sv[nt][1] - mn0);
            float p2 = __expf(sv[nt][2] - mn1);
            float p3 = __expf(sv[nt][3] - mn1);
            l0a += p0 + p1;
            l1a += p2 + p3;
            pf[nt][0] = f2tf(p0);
            pf[nt][1] = f2tf(p2);
            pf[nt][2] = f2tf(p1);
            pf[nt][3] = f2tf(p3);
        }
        l0 = l0 * a0 + l0a;
        l1 = l1 * a1 + l1a;

#pragma unroll
        for (int nt = 0; nt < 16; nt++) {
            o[nt][0] *= a0; o[nt][1] *= a0;
            o[nt][2] *= a1; o[nt][3] *= a1;
        }

#pragma unroll
        for (int s = 0; s < 8; s++) {
            const float* vrow = Vs + (8 * s + 2 * c) * 132 + g;
#pragma unroll
            for (int nt = 0; nt < 16; nt++) {
                unsigned bv[2] = {__float_as_uint(vrow[nt * 8]),
                                  __float_as_uint(vrow[nt * 8 + 132])};
                mma_tf32(o[nt], pf[s], bv);
            }
        }
        __syncthreads();
    }

    l0 += __shfl_xor_sync(0xffffffffu, l0, 1);
    l0 += __shfl_xor_sync(0xffffffffu, l0, 2);
    l1 += __shfl_xor_sync(0xffffffffu, l1, 1);
    l1 += __shfl_xor_sync(0xffffffffu, l1, 2);
    const float inv0 = 1.f / l0;
    const float inv1 = 1.f / l1;

    float* c0 = ctx + ((size_t)b * SEQ + rowg0) * HID + (size_t)h * HDIM;
    float* c1 = ctx + ((size_t)b * SEQ + rowg1) * HID + (size_t)h * HDIM;
#pragma unroll
    for (int nt = 0; nt < 16; nt++) {
        const int col = nt * 8 + 2 * c;
        float2 w0, w1;
        w0.x = __uint_as_float(f2tf(o[nt][0] * inv0));
        w0.y = __uint_as_float(f2tf(o[nt][1] * inv0));
        w1.x = __uint_as_float(f2tf(o[nt][2] * inv1));
        w1.y = __uint_as_float(f2tf(o[nt][3] * inv1));
        *(float2*)(c0 + col) = w0;
        *(float2*)(c1 + col) = w1;
    }
}

// ===========================================================================
extern "C" void kernel_launch(void* const* d_in, const int* in_sizes, int n_in,
                              void* d_out, int out_size) {
    const float* x      = (const float*)d_in[0];
    const float* w_qkv  = (const float*)d_in[1];
    const float* b_qkv  = (const float*)d_in[2];
    const float* w_out  = (const float*)d_in[3];
    const float* b_out  = (const float*)d_in[4];
    float* out = (float*)d_out;

    float* qkv; cudaGetSymbolAddress((void**)&qkv, g_qkv);
    float* ctx; cudaGetSymbolAddress((void**)&ctx, g_ctx);
    float* xt;  cudaGetSymbolAddress((void**)&xt,  g_x);
    float* wq;  cudaGetSymbolAddress((void**)&wq,  g_wq);
    float* wo;  cudaGetSymbolAddress((void**)&wo,  g_wo);

    cudaFuncSetAttribute(sgemm_tf32_kernel<true>,
                         cudaFuncAttributeMaxDynamicSharedMemorySize, G_SMEM_BYTES);
    cudaFuncSetAttribute(sgemm_tf32_kernel<false>,
                         cudaFuncAttributeMaxDynamicSharedMemorySize, G_SMEM_BYTES);
    cudaFuncSetAttribute(flash_attn_tc_kernel,
                         cudaFuncAttributeMaxDynamicSharedMemorySize, AT_SMEM_BYTES);

    // 0) truncate inputs to tf32 once -> mainloops are CVT-free
    trunc_copy_kernel<<<(MROWS * HID / 4) / 256, 256>>>(
        (const float4*)x, (float4*)xt, MROWS * HID / 4);
    trunc_copy_kernel<<<(HID * K3 / 4) / 256, 256>>>(
        (const float4*)w_qkv, (float4*)wq, HID * K3 / 4);
    trunc_copy_kernel<<<(HID * HID / 4) / 256, 256>>>(
        (const float4*)w_out, (float4*)wo, HID * HID / 4);

    // 1) QKV projection (epilogue truncates -> qkv already tf32 bits)
    sgemm_tf32_kernel<true><<<dim3(K3 / 256, MROWS / 128), 256, G_SMEM_BYTES>>>(
        xt, wq, b_qkv, qkv, K3, HID);

    // 2) tensor-core causal flash attention (epilogue truncates ctx)
    flash_attn_tc_kernel<<<dim3(SEQ / 128, NHEAD, BATCH), 256, AT_SMEM_BYTES>>>(qkv, ctx);

    // 3) output projection (fp32 out)
    sgemm_tf32_kernel<false><<<dim3(HID / 256, MROWS / 128), 256, G_SMEM_BYTES>>>(
        ctx, wo, b_out, out, HID, HID);
}

// round 13
// speedup vs baseline: 1.2274x; 1.2274x over previous
#include <cuda_runtime.h>
#include <cstdint>

// Problem constants
#define BATCH 2
#define SEQ   2048
#define HID   2048
#define NHEAD 16
#define HDIM  128
#define MROWS (BATCH * SEQ)   // 4096
#define K3    (3 * HID)       // 6144

// Scratch (allocation-free rule: __device__ globals)
__device__ float g_qkv[(size_t)MROWS * K3];   // [4096, 6144]
__device__ float g_ctx[(size_t)MROWS * HID];  // [4096, 2048]
__device__ float g_x  [(size_t)MROWS * HID];  // tf32-truncated x
__device__ float g_wq [(size_t)HID * K3];     // tf32-truncated w_qkv TRANSPOSED [6144][2048]
__device__ float g_wo [(size_t)HID * HID];    // tf32-truncated w_out TRANSPOSED [2048][2048]

__device__ __forceinline__ unsigned f2tf(float x) {
    unsigned u;
    asm("cvt.rna.tf32.f32 %0, %1;" : "=r"(u) : "f"(x));
    return u;
}

__device__ __forceinline__ void mma_tf32(float* d, const unsigned* a, const unsigned* b) {
    asm volatile(
        "mma.sync.aligned.m16n8k8.row.col.f32.tf32.tf32.f32 "
        "{%0,%1,%2,%3},{%4,%5,%6,%7},{%8,%9},{%0,%1,%2,%3};"
        : "+f"(d[0]), "+f"(d[1]), "+f"(d[2]), "+f"(d[3])
        : "r"(a[0]), "r"(a[1]), "r"(a[2]), "r"(a[3]), "r"(b[0]), "r"(b[1]));
}

__device__ __forceinline__ void cp16(unsigned dst, const void* src) {
    asm volatile("cp.async.cg.shared.global [%0], [%1], 16;\n" :: "r"(dst), "l"(src));
}

// ===========================================================================
// Preprocessing: tf32 truncating copy / truncating transpose
// ===========================================================================
__global__ void trunc_copy_kernel(const float4* __restrict__ src,
                                  float4* __restrict__ dst, int n4) {
    int i = blockIdx.x * blockDim.x + threadIdx.x;
    if (i < n4) {
        float4 v = src[i];
        v.x = __uint_as_float(f2tf(v.x));
        v.y = __uint_as_float(f2tf(v.y));
        v.z = __uint_as_float(f2tf(v.z));
        v.w = __uint_as_float(f2tf(v.w));
        dst[i] = v;
    }
}

// src[R][C] -> dst[C][R], truncated to tf32
__global__ void trunc_transpose_kernel(const float* __restrict__ src,
                                       float* __restrict__ dst, int R, int C) {
    __shared__ float t[32][33];
    const int c0 = blockIdx.x * 32, r0 = blockIdx.y * 32;
    const int tx = threadIdx.x, ty = threadIdx.y;
#pragma unroll
    for (int j = 0; j < 32; j += 8)
        t[ty + j][tx] = src[(size_t)(r0 + ty + j) * C + c0 + tx];
    __syncthreads();
#pragma unroll
    for (int j = 0; j < 32; j += 8)
        dst[(size_t)(c0 + ty + j) * R + r0 + tx] = __uint_as_float(f2tf(t[tx][ty + j]));
}

// ===========================================================================
// tf32 mma.sync GEMM: C[M,N] = A[M,K] @ Bt[N,K]^T + bias
// Block 128x128, BK=32, 256 threads (8 warps 2m x 4n, warp tile 64x32).
// A smem [m][32k] and B smem [n][32k], both XOR-swizzled identically ->
// all fragment reads are phase-conflict-free LDS.64.
// 3-stage cp.async pipeline, ONE __syncthreads per iter.
// Inputs pre-truncated to tf32 (zero CVT in mainloop).
// ===========================================================================
#define GA_W 4096                    // A stage words (128*32)
#define GSTAGE_W 8192                // A + B stage words (32KB)
#define G_SMEM_BYTES (3 * GSTAGE_W * 4)   // 98304

template <bool TRUNC_OUT>
__global__ __launch_bounds__(256, 2)
void sgemm_tf32_kernel(const float* __restrict__ A, const float* __restrict__ Bt,
                       const float* __restrict__ bias, float* __restrict__ C,
                       int N, int K) {
    extern __shared__ float sm[];
    const int tid = threadIdx.x;
    const int lane = tid & 31;
    const int warp = tid >> 5;
    const int wm = warp & 1;        // 0..1  (64-row half)
    const int wn = warp >> 1;       // 0..3  (32-col quarter)
    const int bm = blockIdx.y * 128;
    const int bn = blockIdx.x * 128;

    const int g = lane >> 2;        // 0..7
    const int c = lane & 3;         // 0..3
    const int swz = (g & 3) * 8;

    unsigned smu;
    { unsigned long long p = __cvta_generic_to_shared(sm); smu = (unsigned)p; }

    // copy mapping: A 4 chunks, B 4 chunks of 16B per stage
    // chunk a = tid + 256*r : row = a>>3 (0..127), cc = a&7 (16B chunk in 128B row)
    unsigned aDst[4]; const float* aSrc[4];
    unsigned bDst[4]; const float* bSrc[4];
#pragma unroll
    for (int r = 0; r < 4; r++) {
        int a = tid + 256 * r;
        int row = a >> 3, cc = a & 7;
        unsigned sw = (unsigned)(row * 32 + ((cc * 4) ^ ((row & 3) * 8))) * 4;
        aDst[r] = smu + sw;
        bDst[r] = smu + (unsigned)(GA_W * 4) + sw;
        aSrc[r] = A  + (size_t)(bm + row) * K + cc * 4;
        bSrc[r] = Bt + (size_t)(bn + row) * K + cc * 4;
    }

    float acc[4][4][4];
#pragma unroll
    for (int mt = 0; mt < 4; mt++)
#pragma unroll
        for (int nt = 0; nt < 4; nt++)
#pragma unroll
            for (int r = 0; r < 4; r++) acc[mt][nt][r] = 0.f;

    const int T = K / 32;

    auto issue = [&](int i) {
        const unsigned so = (unsigned)((i % 3) * GSTAGE_W) * 4;
        const int k0 = i * 32;
#pragma unroll
        for (int r = 0; r < 4; r++) {
            cp16(aDst[r] + so, aSrc[r] + k0);
            cp16(bDst[r] + so, bSrc[r] + k0);
        }
    };

    issue(0);
    asm volatile("cp.async.commit_group;\n");
    issue(1);
    asm volatile("cp.async.commit_group;\n");

    for (int i = 0; i < T; i++) {
        asm volatile("cp.async.wait_group 1;\n");
        __syncthreads();

        if (i + 2 < T) issue(i + 2);
        asm volatile("cp.async.commit_group;\n");

        const float* As = sm + (i % 3) * GSTAGE_W;
        const float* Bs = As + GA_W;

#pragma unroll
        for (int s = 0; s < 4; s++) {
            const int kof = (8 * s + 2 * c) ^ swz;
            unsigned av[4][4];
#pragma unroll
            for (int mt = 0; mt < 4; mt++) {
                const float* pa = As + (wm * 64 + mt * 16 + g) * 32 + kof;
                float2 f0 = *(const float2*)pa;
                float2 f1 = *(const float2*)(pa + 8 * 32);
                av[mt][0] = __float_as_uint(f0.x);
                av[mt][2] = __float_as_uint(f0.y);
                av[mt][1] = __float_as_uint(f1.x);
                av[mt][3] = __float_as_uint(f1.y);
            }
            unsigned bv[4][2];
#pragma unroll
            for (int nt = 0; nt < 4; nt++) {
                const float* pb = Bs + (wn * 32 + nt * 8 + g) * 32 + kof;
                float2 kf = *(const float2*)pb;
                bv[nt][0] = __float_as_uint(kf.x);
                bv[nt][1] = __float_as_uint(kf.y);
            }
#pragma unroll
            for (int mt = 0; mt < 4; mt++)
#pragma unroll
                for (int nt = 0; nt < 4; nt++)
                    mma_tf32(acc[mt][nt], av[mt], bv[nt]);
        }
    }

    // epilogue: add bias, write float2 pairs
#pragma unroll
    for (int mt = 0; mt < 4; mt++) {
        const int row = bm + wm * 64 + mt * 16 + g;
#pragma unroll
        for (int nt = 0; nt < 4; nt++) {
            const int col = bn + wn * 32 + nt * 8 + 2 * c;
            const float b0 = __ldg(&bias[col]);
            const float b1 = __ldg(&bias[col + 1]);
            float v00 = acc[mt][nt][0] + b0, v01 = acc[mt][nt][1] + b1;
            float v10 = acc[mt][nt][2] + b0, v11 = acc[mt][nt][3] + b1;
            if (TRUNC_OUT) {
                v00 = __uint_as_float(f2tf(v00));
                v01 = __uint_as_float(f2tf(v01));
                v10 = __uint_as_float(f2tf(v10));
                v11 = __uint_as_float(f2tf(v11));
            }
            float2 o0 = {v00, v01}, o1 = {v10, v11};
            *(float2*)(C + (size_t)row * N + col) = o0;
            *(float2*)(C + (size_t)(row + 8) * N + col) = o1;
        }
    }
}

// ===========================================================================
// Tensor-core causal flash attention (tf32 mma.sync) — round 5 version
// ===========================================================================
#define K_STW 8192
#define V_STW 8448
#define V_BASE_W 16384
#define AT_SMEM_BYTES ((V_BASE_W + 2 * V_STW) * 4)   // 133120

__global__ __launch_bounds__(256, 1)
void flash_attn_tc_kernel(const float* __restrict__ qkv, float* __restrict__ ctx) {
    extern __shared__ float sm[];
    const int tid = threadIdx.x;
    const int lane = tid & 31;
    const int wid = tid >> 5;
    const int g = lane >> 2;
    const int c = lane & 3;
    const int qt = 15 - blockIdx.x;
    const int h = blockIdx.y;
    const int b = blockIdx.z;
    const int q0 = qt * 128;
    const float scale = 0.08838834764831845f;

    const float* base = qkv + ((size_t)b * SEQ) * K3 + (size_t)h * (3 * HDIM);

    unsigned smu;
    { unsigned long long p = __cvta_generic_to_shared(sm); smu = (unsigned)p; }

    const int ntiles = 2 * qt + 2;

    auto issue_tile = [&](int j, int st) {
        const float* kvb = base + (size_t)(j * 64) * K3;
#pragma unroll
        for (int r = 0; r < 8; r++) {
            int chunk = tid + 256 * r;
            int row = chunk >> 5;
            int cw = (chunk & 31) * 4;
            const float* src = kvb + (size_t)row * K3 + cw;
            unsigned kd = smu + (unsigned)(st * K_STW + row * 128 + (cw ^ ((row & 3) * 8))) * 4;
            unsigned vd = smu + (unsigned)(V_BASE_W + st * V_STW + row * 132 + cw) * 4;
            cp16(kd, src + HDIM);
            cp16(vd, src + 2 * HDIM);
        }
    };

    issue_tile(0, 0);
    asm volatile("cp.async.commit_group;\n");

    unsigned qf[16][4];
    {
        const float* qrow = base + (size_t)(q0 + wid * 16 + g) * K3;
        const float* qrow8 = qrow + 8 * (size_t)K3;
#pragma unroll
        for (int s = 0; s < 16; s++) {
            float2 f0 = *(const float2*)(qrow + 8 * s + 2 * c);
            float2 f1 = *(const float2*)(qrow8 + 8 * s + 2 * c);
            qf[s][0] = __float_as_uint(f0.x);
            qf[s][2] = __float_as_uint(f0.y);
            qf[s][1] = __float_as_uint(f1.x);
            qf[s][3] = __float_as_uint(f1.y);
        }
    }

    float o[16][4];
#pragma unroll
    for (int nt = 0; nt < 16; nt++)
#pragma unroll
        for (int r = 0; r < 4; r++) o[nt][r] = 0.f;
    float m0 = -1e30f, m1 = -1e30f, l0 = 0.f, l1 = 0.f;

    const int rowg0 = q0 + wid * 16 + g;
    const int rowg1 = rowg0 + 8;

    for (int j = 0; j < ntiles; j++) {
        if (j + 1 < ntiles) issue_tile(j + 1, (j + 1) & 1);
        asm volatile("cp.async.commit_group;\n");
        asm volatile("cp.async.wait_group 1;\n");
        __syncthreads();

        const int st = j & 1;
        const float* Ks = sm + st * K_STW;
        const float* Vs = sm + V_BASE_W + st * V_STW;

        float sv[8][4];
#pragma unroll
        for (int nt = 0; nt < 8; nt++)
#pragma unroll
            for (int r = 0; r < 4; r++) sv[nt][r] = 0.f;

#pragma unroll
        for (int s = 0; s < 16; s++) {
            const int kof = (8 * s + 2 * c) ^ ((g & 3) * 8);
#pragma unroll
            for (int nt = 0; nt < 8; nt++) {
                float2 kf = *(const float2*)(Ks + (nt * 8 + g) * 128 + kof);
                unsigned bv[2] = {__float_as_uint(kf.x), __float_as_uint(kf.y)};
                mma_tf32(sv[nt], qf[s], bv);
            }
        }

#pragma unroll
        for (int nt = 0; nt < 8; nt++)
#pragma unroll
            for (int r = 0; r < 4; r++) sv[nt][r] *= scale;

        if (j >= 2 * qt) {
            const int kv0 = j * 64;
#pragma unroll
            for (int nt = 0; nt < 8; nt++) {
                const int col = kv0 + nt * 8 + 2 * c;
                if (col     > rowg0) sv[nt][0] = -1e30f;
                if (col + 1 > rowg0) sv[nt][1] = -1e30f;
                if (col     > rowg1) sv[nt][2] = -1e30f;
                if (col + 1 > rowg1) sv[nt][3] = -1e30f;
            }
        }

        float mx0 = -1e30f, mx1 = -1e30f;
#pragma unroll
        for (int nt = 0; nt < 8; nt++) {
            mx0 = fmaxf(mx0, fmaxf(sv[nt][0], sv[nt][1]));
            mx1 = fmaxf(mx1, fmaxf(sv[nt][2], sv[nt][3]));
        }
        mx0 = fmaxf(mx0, __shfl_xor_sync(0xffffffffu, mx0, 1));
        mx0 = fmaxf(mx0, __shfl_xor_sync(0xffffffffu, mx0, 2));
        mx1 = fmaxf(mx1, __shfl_xor_sync(0xffffffffu, mx1, 1));
        mx1 = fmaxf(mx1, __shfl_xor_sync(0xffffffffu, mx1, 2));

        const float mn0 = fmaxf(m0, mx0);
        const float mn1 = fmaxf(m1, mx1);
        const float a0 = __expf(m0 - mn0);
        const float a1 = __expf(m1 - mn1);
        m0 = mn0; m1 = mn1;

        float l0a = 0.f, l1a = 0.f;
        unsigned pf[8][4];
#pragma unroll
        for (int nt = 0; nt < 8; nt++) {
            float p0 = __expf(sv[nt][0] - mn0);
            float p1 = __expf(sv[nt][1] - mn0);
            float p2 = __expf(sv[nt][2] - mn1);
            float p3 = __expf(sv[nt][3] - mn1);
            l0a += p0 + p1;
            l1a += p2 + p3;
            pf[nt][0] = f2tf(p0);
            pf[nt][1] = f2tf(p2);
            pf[nt][2] = f2tf(p1);
            pf[nt][3] = f2tf(p3);
        }
        l0 = l0 * a0 + l0a;
        l1 = l1 * a1 + l1a;

#pragma unroll
        for (int nt = 0; nt < 16; nt++) {
            o[nt][0] *= a0; o[nt][1] *= a0;
            o[nt][2] *= a1; o[nt][3] *= a1;
        }

#pragma unroll
        for (int s = 0; s < 8; s++) {
            const float* vrow = Vs + (8 * s + 2 * c) * 132 + g;
#pragma unroll
            for (int nt = 0; nt < 16; nt++) {
                unsigned bv[2] = {__float_as_uint(vrow[nt * 8]),
                                  __float_as_uint(vrow[nt * 8 + 132])};
                mma_tf32(o[nt], pf[s], bv);
            }
        }
        __syncthreads();
    }

    l0 += __shfl_xor_sync(0xffffffffu, l0, 1);
    l0 += __shfl_xor_sync(0xffffffffu, l0, 2);
    l1 += __shfl_xor_sync(0xffffffffu, l1, 1);
    l1 += __shfl_xor_sync(0xffffffffu, l1, 2);
    const float inv0 = 1.f / l0;
    const float inv1 = 1.f / l1;

    float* c0 = ctx + ((size_t)b * SEQ + rowg0) * HID + (size_t)h * HDIM;
    float* c1 = ctx + ((size_t)b * SEQ + rowg1) * HID + (size_t)h * HDIM;
#pragma unroll
    for (int nt = 0; nt < 16; nt++) {
        const int col = nt * 8 + 2 * c;
        float2 w0, w1;
        w0.x = __uint_as_float(f2tf(o[nt][0] * inv0));
        w0.y = __uint_as_float(f2tf(o[nt][1] * inv0));
        w1.x = __uint_as_float(f2tf(o[nt][2] * inv1));
        w1.y = __uint_as_float(f2tf(o[nt][3] * inv1));
        *(float2*)(c0 + col) = w0;
        *(float2*)(c1 + col) = w1;
    }
}

// ===========================================================================
extern "C" void kernel_launch(void* const* d_in, const int* in_sizes, int n_in,
                              void* d_out, int out_size) {
    const float* x      = (const float*)d_in[0];
    const float* w_qkv  = (const float*)d_in[1];
    const float* b_qkv  = (const float*)d_in[2];
    const float* w_out  = (const float*)d_in[3];
    const float* b_out  = (const float*)d_in[4];
    float* out = (float*)d_out;

    float* qkv; cudaGetSymbolAddress((void**)&qkv, g_qkv);
    float* ctx; cudaGetSymbolAddress((void**)&ctx, g_ctx);
    float* xt;  cudaGetSymbolAddress((void**)&xt,  g_x);
    float* wqT; cudaGetSymbolAddress((void**)&wqT, g_wq);
    float* woT; cudaGetSymbolAddress((void**)&woT, g_wo);

    cudaFuncSetAttribute(sgemm_tf32_kernel<true>,
                         cudaFuncAttributeMaxDynamicSharedMemorySize, G_SMEM_BYTES);
    cudaFuncSetAttribute(sgemm_tf32_kernel<false>,
                         cudaFuncAttributeMaxDynamicSharedMemorySize, G_SMEM_BYTES);
    cudaFuncSetAttribute(flash_attn_tc_kernel,
                         cudaFuncAttributeMaxDynamicSharedMemorySize, AT_SMEM_BYTES);

    // 0) preprocess: truncate x; truncate+transpose weights to [N][K]
    trunc_copy_kernel<<<(MROWS * HID / 4) / 256, 256>>>(
        (const float4*)x, (float4*)xt, MROWS * HID / 4);
    trunc_transpose_kernel<<<dim3(K3 / 32, HID / 32), dim3(32, 8)>>>(w_qkv, wqT, HID, K3);
    trunc_transpose_kernel<<<dim3(HID / 32, HID / 32), dim3(32, 8)>>>(w_out, woT, HID, HID);

    // 1) QKV projection (epilogue truncates -> qkv already tf32 bits)
    sgemm_tf32_kernel<true><<<dim3(K3 / 128, MROWS / 128), 256, G_SMEM_BYTES>>>(
        xt, wqT, b_qkv, qkv, K3, HID);

    // 2) tensor-core causal flash attention (epilogue truncates ctx)
    flash_attn_tc_kernel<<<dim3(SEQ / 128, NHEAD, BATCH), 256, AT_SMEM_BYTES>>>(qkv, ctx);

    // 3) output projection (fp32 out)
    sgemm_tf32_kernel<false><<<dim3(HID / 128, MROWS / 128), 256, G_SMEM_BYTES>>>(
        ctx, woT, b_out, out, HID, HID);
}